// round 1
// baseline (speedup 1.0000x reference)
#include <cuda_runtime.h>
#include <cstdint>
#include <cstddef>

// Problem constants
#define PB 256
#define PT 1024
#define PD 128
#define PH 256
#define BT (PB * PT)   // 262144 tokens

// ---------------- scratch (device globals; no cudaMalloc allowed) ----------
__device__ float g_sig[(size_t)BT * PH];   // sigmoid(x@Wx+bx), later gate (256 MB)
__device__ float g_a[(size_t)BT * 100];    // MLP ping (105 MB)
__device__ float g_b[(size_t)BT * 100];    // MLP pong (105 MB)

__device__ __forceinline__ float sigf(float x) { return 1.f / (1.f + __expf(-x)); }

// ---------------- generic fused SGEMM:  C = act(A[MxK] @ W[KxN] + bias) ----
// MODE 1: sigmoid(store)   MODE 2: relu(store)   MODE 3: C = sigmoid(.)*C (in place gate)
#define BK 16
#define BM 64
#define BN 64

template <int MODE>
__global__ void __launch_bounds__(256)
gemm_kernel(const float* __restrict__ A, const float* __restrict__ W,
            const float* __restrict__ bias, float* __restrict__ C,
            int M, int K, int N)
{
    __shared__ float As[BK][BM];
    __shared__ float Bs[BK][BN];

    const int tid = threadIdx.x;
    const int tx = tid & 15;       // 0..15  -> 4 cols each
    const int ty = tid >> 4;       // 0..15  -> 4 rows each
    const int rowBase = blockIdx.y * BM;
    const int colBase = blockIdx.x * BN;

    float acc[4][4] = {};

    const int a_r  = tid >> 2;        // 0..63
    const int a_k0 = (tid & 3) * 4;   // 0,4,8,12
    const int b_k  = tid >> 4;        // 0..15
    const int b_c0 = (tid & 15) * 4;  // 0..60

    const int nk = (K + BK - 1) / BK;
    for (int kb = 0; kb < nk; kb++) {
        const int k0 = kb * BK;
        // load A tile (transposed into As[k][row])
        #pragma unroll
        for (int i = 0; i < 4; i++) {
            int gk = k0 + a_k0 + i;
            As[a_k0 + i][a_r] = (gk < K) ? A[(size_t)(rowBase + a_r) * K + gk] : 0.f;
        }
        // load B tile
        {
            int gk = k0 + b_k;
            #pragma unroll
            for (int i = 0; i < 4; i++) {
                int gc = colBase + b_c0 + i;
                Bs[b_k][b_c0 + i] = (gk < K && gc < N) ? W[(size_t)gk * N + gc] : 0.f;
            }
        }
        __syncthreads();

        #pragma unroll
        for (int kk = 0; kk < BK; kk++) {
            float4 av = *(const float4*)&As[kk][ty * 4];
            float4 bv = *(const float4*)&Bs[kk][tx * 4];
            float a4[4] = {av.x, av.y, av.z, av.w};
            float b4[4] = {bv.x, bv.y, bv.z, bv.w};
            #pragma unroll
            for (int ii = 0; ii < 4; ii++)
                #pragma unroll
                for (int jj = 0; jj < 4; jj++)
                    acc[ii][jj] = fmaf(a4[ii], b4[jj], acc[ii][jj]);
        }
        __syncthreads();
    }

    // epilogue (M is always a multiple of BM here; guard columns only)
    #pragma unroll
    for (int ii = 0; ii < 4; ii++) {
        int row = rowBase + ty * 4 + ii;
        #pragma unroll
        for (int jj = 0; jj < 4; jj++) {
            int col = colBase + tx * 4 + jj;
            if (col < N) {
                float v = acc[ii][jj] + bias[col];
                size_t idx = (size_t)row * N + col;
                if (MODE == 1)      v = sigf(v);
                else if (MODE == 2) v = fmaxf(v, 0.f);
                else                v = sigf(v) * C[idx];   // gate = fx * sig(lin)
                C[idx] = v;
            }
        }
    }
}

// ---------------- sequential scan: one warp per batch, 8 h per lane --------
// rolled[i] = hid[(i-1) mod H]; lane owns h = lane*8 .. lane*8+7
__device__ __forceinline__ void scan_load(const float* __restrict__ gb,
                                          float4 buf[8][2], int c)
{
    #pragma unroll
    for (int tt = 0; tt < 8; tt++) {
        const float4* p = (const float4*)(gb + (size_t)(c * 8 + tt) * PH);
        buf[tt][0] = p[0];
        buf[tt][1] = p[1];
    }
}

__device__ __forceinline__ void scan_proc(float4 buf[8][2], float s[8], int lane)
{
    #pragma unroll
    for (int tt = 0; tt < 8; tt++) {
        const float g0 = buf[tt][0].x, g1 = buf[tt][0].y,
                    g2 = buf[tt][0].z, g3 = buf[tt][0].w;
        const float g4 = buf[tt][1].x, g5 = buf[tt][1].y,
                    g6 = buf[tt][1].z, g7 = buf[tt][1].w;
        // old s[7] from lane-1 (wraps: lane 0 reads lane 31 == h 255)
        float carry = __shfl_sync(0xffffffffu, s[7], (lane + 31) & 31);
        s[7] = fmaxf(s[6] + g7, 0.f);
        s[6] = fmaxf(s[5] + g6, 0.f);
        s[5] = fmaxf(s[4] + g5, 0.f);
        s[4] = fmaxf(s[3] + g4, 0.f);
        s[3] = fmaxf(s[2] + g3, 0.f);
        s[2] = fmaxf(s[1] + g2, 0.f);
        s[1] = fmaxf(s[0] + g1, 0.f);
        s[0] = fmaxf(carry + g0, 0.f);
    }
}

__global__ void __launch_bounds__(32)
scan_kernel(const float* __restrict__ gate, const float* __restrict__ Wo,
            const float* __restrict__ bo, float* __restrict__ out)
{
    const int b = blockIdx.x;
    const int lane = threadIdx.x;
    const float* gb = gate + (size_t)b * PT * PH + lane * 8;

    float s[8];
    #pragma unroll
    for (int j = 0; j < 8; j++) s[j] = 0.f;

    float4 bufA[8][2], bufB[8][2];
    const int nc = PT / 8;   // 128 chunks of 8 timesteps

    scan_load(gb, bufA, 0);
    for (int c = 0; c < nc; c += 2) {
        if (c + 1 < nc) scan_load(gb, bufB, c + 1);   // prefetch while A in flight
        scan_proc(bufA, s, lane);
        if (c + 2 < nc) scan_load(gb, bufA, c + 2);
        if (c + 1 < nc) scan_proc(bufB, s, lane);
    }

    // output = sigmoid(hidden @ Wo + bo)
    float part = 0.f;
    #pragma unroll
    for (int j = 0; j < 8; j++) part = fmaf(s[j], Wo[lane * 8 + j], part);
    #pragma unroll
    for (int off = 16; off; off >>= 1)
        part += __shfl_xor_sync(0xffffffffu, part, off);
    if (lane == 0) out[b] = 1.f / (1.f + __expf(-(part + bo[0])));

    // hidden -> d_out[B : B + B*H]
    float* hid = out + PB + (size_t)b * PH + lane * 8;
    #pragma unroll
    for (int j = 0; j < 8; j++) hid[j] = s[j];
}

// ---------------- launch -------------------------------------------------
extern "C" void kernel_launch(void* const* d_in, const int* in_sizes, int n_in,
                              void* d_out, int out_size)
{
    const float* x  = (const float*)d_in[0];
    const float* Wx = (const float*)d_in[1];
    const float* bx = (const float*)d_in[2];
    const float* W1 = (const float*)d_in[3];
    const float* b1 = (const float*)d_in[4];
    const float* W2 = (const float*)d_in[5];
    const float* b2 = (const float*)d_in[6];
    const float* W3 = (const float*)d_in[7];
    const float* b3 = (const float*)d_in[8];
    const float* W4 = (const float*)d_in[9];
    const float* b4 = (const float*)d_in[10];
    const float* W5 = (const float*)d_in[11];
    const float* b5 = (const float*)d_in[12];
    const float* Wo = (const float*)d_in[13];
    const float* bo = (const float*)d_in[14];
    float* out = (float*)d_out;

    void *p_sig, *p_a, *p_b;
    cudaGetSymbolAddress(&p_sig, g_sig);
    cudaGetSymbolAddress(&p_a, g_a);
    cudaGetSymbolAddress(&p_b, g_b);
    float* sig = (float*)p_sig;
    float* va  = (float*)p_a;
    float* vb  = (float*)p_b;

    const int M = BT;
    dim3 blk(256);
    dim3 gMy(0, M / BM);

    // 1) sig(lin_x): [BT,128] @ [128,256]
    gemm_kernel<1><<<dim3(4, M / BM), blk>>>(x, Wx, bx, sig, M, PD, PH);
    // 2-5) MLP chain
    gemm_kernel<2><<<dim3(2, M / BM), blk>>>(x,  W1, b1, va, M, 128, 100);
    gemm_kernel<2><<<dim3(2, M / BM), blk>>>(va, W2, b2, vb, M, 100, 100);
    gemm_kernel<2><<<dim3(2, M / BM), blk>>>(vb, W3, b3, va, M, 100, 100);
    gemm_kernel<2><<<dim3(1, M / BM), blk>>>(va, W4, b4, vb, M, 100,  50);
    // 6) gate = sigmoid(h@W5+b5) * sig(lin_x), in place into sig
    gemm_kernel<3><<<dim3(4, M / BM), blk>>>(vb, W5, b5, sig, M,  50, PH);
    // 7) sequential scan + output head
    scan_kernel<<<PB, 32>>>(sig, Wo, bo, out);
}

// round 5
// speedup vs baseline: 2.6205x; 2.6205x over previous
#include <cuda_runtime.h>
#include <cstdint>
#include <cstddef>

#define PB 256
#define PT 1024
#define PD 128
#define PH 256
#define BT (PB * PT)   // 262144 tokens

// ---------------- scratch (device globals; no cudaMalloc allowed) ----------
__device__ float g_sig[(size_t)BT * PH];   // sigmoid(x@Wx+bx), later gate (256 MB)
__device__ float g_a[(size_t)BT * 128];    // MLP ping (padded to 128)
__device__ float g_b[(size_t)BT * 128];    // MLP pong
__device__ float g_c[(size_t)BT * 64];     // layer-4 out (padded to 64)
__device__ float g_pA[2048 * 256];         // scan partials
__device__ float g_pB[2048 * 256];

// padded, transposed ([N, K] K-major) weights
__device__ float g_WxT[256 * 128];
__device__ float g_W1T[128 * 128];
__device__ float g_W2T[128 * 128];
__device__ float g_W3T[128 * 128];
__device__ float g_W4T[64 * 128];
__device__ float g_W5T[256 * 64];
__device__ float g_b1p[128], g_b2p[128], g_b3p[128], g_b4p[64];

__device__ __forceinline__ float sigf(float x) { return 1.f / (1.f + __expf(-x)); }

__device__ __forceinline__ uint32_t smem_u32(const void* p) {
    uint32_t a;
    asm("{ .reg .u64 t; cvta.to.shared.u64 t, %1; cvt.u32.u64 %0, t; }" : "=r"(a) : "l"(p));
    return a;
}
__device__ __forceinline__ void cp16(uint32_t dst, const void* src) {
    asm volatile("cp.async.ca.shared.global [%0], [%1], 16;" :: "r"(dst), "l"(src) : "memory");
}
__device__ __forceinline__ void cp_commit() {
    asm volatile("cp.async.commit_group;" ::: "memory");
}
template <int N>
__device__ __forceinline__ void cp_wait() {
    asm volatile("cp.async.wait_group %0;" :: "n"(N) : "memory");
}
__device__ __forceinline__ uint32_t f2tf(float x) {
    uint32_t u;
    asm("cvt.rna.tf32.f32 %0, %1;" : "=r"(u) : "f"(x));
    return u;
}
__device__ __forceinline__ void mma8(float* c, const uint32_t* a, uint32_t b0, uint32_t b1) {
    asm volatile(
        "mma.sync.aligned.m16n8k8.row.col.f32.tf32.tf32.f32 "
        "{%0,%1,%2,%3}, {%4,%5,%6,%7}, {%8,%9}, {%0,%1,%2,%3};"
        : "+f"(c[0]), "+f"(c[1]), "+f"(c[2]), "+f"(c[3])
        : "r"(a[0]), "r"(a[1]), "r"(a[2]), "r"(a[3]), "r"(b0), "r"(b1));
}

// ---------------- weight prep: transpose + pad -----------------------------
__global__ void prep_kernel(const float* __restrict__ Wx,
                            const float* __restrict__ W1, const float* __restrict__ b1,
                            const float* __restrict__ W2, const float* __restrict__ b2,
                            const float* __restrict__ W3, const float* __restrict__ b3,
                            const float* __restrict__ W4, const float* __restrict__ b4,
                            const float* __restrict__ W5)
{
    int t = blockIdx.x * blockDim.x + threadIdx.x;
    int S = gridDim.x * blockDim.x;
    for (int i = t; i < 256 * 128; i += S) { int n = i >> 7, k = i & 127; g_WxT[i] = Wx[k * 256 + n]; }
    for (int i = t; i < 128 * 128; i += S) { int n = i >> 7, k = i & 127; g_W1T[i] = (n < 100) ? W1[k * 100 + n] : 0.f; }
    for (int i = t; i < 128 * 128; i += S) { int n = i >> 7, k = i & 127; g_W2T[i] = (n < 100 && k < 100) ? W2[k * 100 + n] : 0.f; }
    for (int i = t; i < 128 * 128; i += S) { int n = i >> 7, k = i & 127; g_W3T[i] = (n < 100 && k < 100) ? W3[k * 100 + n] : 0.f; }
    for (int i = t; i < 64 * 128;  i += S) { int n = i >> 7, k = i & 127; g_W4T[i] = (n < 50 && k < 100) ? W4[k * 50 + n] : 0.f; }
    for (int i = t; i < 256 * 64;  i += S) { int n = i >> 6, k = i & 63;  g_W5T[i] = (k < 50) ? W5[k * 256 + n] : 0.f; }
    for (int i = t; i < 128; i += S) {
        g_b1p[i] = (i < 100) ? b1[i] : 0.f;
        g_b2p[i] = (i < 100) ? b2[i] : 0.f;
        g_b3p[i] = (i < 100) ? b3[i] : 0.f;
    }
    for (int i = t; i < 64; i += S) g_b4p[i] = (i < 50) ? b4[i] : 0.f;
}

// ---------------- mma.sync tf32 GEMM ---------------------------------------
// C[128, BN] tile = act(A[128, K] @ Bw[N, K]^T + bias)
// MODE 1: sigmoid   MODE 2: relu   MODE 3: C = sigmoid(.) * C (in place gate)
// A row-major pitch K; Bw row-major [N][K] (K-major weights); C pitch NFULL.
template <int K, int NFULL, int BN, int MODE>
__global__ void __launch_bounds__(256, 1)
mma_gemm(const float* __restrict__ A, const float* __restrict__ Bw,
         const float* __restrict__ bias, float* __restrict__ C)
{
    constexpr int KP = K + 4;       // smem pitch (floats)
    constexpr int KC = K / 2;       // k-chunk for cp.async pipeline
    constexpr int WN = BN / 2;      // warp N tile
    constexpr int NT = WN / 8;      // n mma-tiles per warp
    extern __shared__ float sm[];
    float* As = sm;                 // [128][KP]
    float* Bs = sm + 128 * KP;      // [BN][KP]
    const uint32_t sbase = smem_u32(sm);

    const int tid = threadIdx.x;
    const int lane = tid & 31;
    const int wid = tid >> 5;
    const int g = lane >> 2, tig = lane & 3;
    const int wm = wid & 3, wn = wid >> 2;
    const size_t rowBase = (size_t)blockIdx.y * 128;
    const int colBase = blockIdx.x * BN;

    // ---- async-load both K-chunks (chunk1 overlaps chunk0 compute) ----
    #pragma unroll
    for (int ch = 0; ch < 2; ch++) {
        const int kc0 = ch * KC;
        #pragma unroll
        for (int id = tid; id < 128 * (KC / 4); id += 256) {
            int r = id / (KC / 4), kv = (id % (KC / 4)) * 4;
            cp16(sbase + (uint32_t)(r * KP + kc0 + kv) * 4u,
                 A + (rowBase + r) * K + kc0 + kv);
        }
        #pragma unroll
        for (int id = tid; id < BN * (KC / 4); id += 256) {
            int r = id / (KC / 4), kv = (id % (KC / 4)) * 4;
            cp16(sbase + (uint32_t)((128 + r) * KP + kc0 + kv) * 4u,
                 Bw + (size_t)(colBase + r) * K + kc0 + kv);
        }
        cp_commit();
    }

    float acc[2][NT][4];
    #pragma unroll
    for (int mt = 0; mt < 2; mt++)
        #pragma unroll
        for (int nt = 0; nt < NT; nt++)
            #pragma unroll
            for (int j = 0; j < 4; j++) acc[mt][nt][j] = 0.f;

    #pragma unroll
    for (int ch = 0; ch < 2; ch++) {
        if (ch == 0) cp_wait<1>(); else cp_wait<0>();
        __syncthreads();
        #pragma unroll
        for (int s = 0; s < KC / 8; s++) {
            const int k0 = ch * KC + s * 8;
            uint32_t af[2][4];
            #pragma unroll
            for (int mt = 0; mt < 2; mt++) {
                const float* ap = As + (wm * 32 + mt * 16 + g) * KP + k0 + tig;
                af[mt][0] = f2tf(ap[0]);
                af[mt][1] = f2tf(ap[8 * KP]);
                af[mt][2] = f2tf(ap[4]);
                af[mt][3] = f2tf(ap[8 * KP + 4]);
            }
            #pragma unroll
            for (int nt = 0; nt < NT; nt++) {
                const float* bp = Bs + (wn * WN + nt * 8 + g) * KP + k0 + tig;
                uint32_t b0 = f2tf(bp[0]);
                uint32_t b1 = f2tf(bp[4]);
                mma8(acc[0][nt], af[0], b0, b1);
                mma8(acc[1][nt], af[1], b0, b1);
            }
        }
    }

    // ---- fused epilogue ----
    #pragma unroll
    for (int mt = 0; mt < 2; mt++) {
        #pragma unroll
        for (int nt = 0; nt < NT; nt++) {
            const int c0 = colBase + wn * WN + nt * 8 + 2 * tig;
            const float bx0 = __ldg(bias + c0), bx1 = __ldg(bias + c0 + 1);
            #pragma unroll
            for (int h = 0; h < 2; h++) {
                const size_t r = rowBase + wm * 32 + mt * 16 + g + h * 8;
                float v0 = acc[mt][nt][2 * h + 0] + bx0;
                float v1 = acc[mt][nt][2 * h + 1] + bx1;
                float2* cp = (float2*)(C + r * NFULL + c0);
                if (MODE == 1)      { v0 = sigf(v0); v1 = sigf(v1); }
                else if (MODE == 2) { v0 = fmaxf(v0, 0.f); v1 = fmaxf(v1, 0.f); }
                else {
                    float2 old = *cp;
                    v0 = sigf(v0) * old.x;
                    v1 = sigf(v1) * old.y;
                }
                *cp = make_float2(v0, v1);
            }
        }
    }
}

// ---------------- scan as max-plus reduction --------------------------------
// Per final coordinate i the recurrence follows a diagonal scalar chain
// v <- max(v + a_t, 0) with a_t = gate[b][t][(i + t + 1) & 255].
// f(v)=max(v+A,B) composes: (A,B)*(A',B') = (A+A', max(B+A', B')).
__global__ void __launch_bounds__(256)
scan_part(const float* __restrict__ gate, float* __restrict__ pA, float* __restrict__ pB)
{
    const int b = blockIdx.x >> 3, c = blockIdx.x & 7;
    const int i = threadIdx.x;
    const float* gb = gate + ((size_t)b << 18);
    float Aacc = 0.f, Bacc = -3.0e38f;
    const int t0 = c * 128;
    #pragma unroll 8
    for (int t = t0; t < t0 + 128; t++) {
        float val = gb[(size_t)t * 256 + ((i + t + 1) & 255)];
        Aacc += val;
        Bacc = fmaxf(Bacc + val, 0.f);
    }
    const int o = blockIdx.x * 256 + i;
    pA[o] = Aacc;
    pB[o] = Bacc;
}

__global__ void __launch_bounds__(256)
scan_fin(const float* __restrict__ pA, const float* __restrict__ pB,
         const float* __restrict__ Wo, const float* __restrict__ bo,
         float* __restrict__ out)
{
    const int b = blockIdx.x, i = threadIdx.x;
    float A = 0.f, B = -3.0e38f;
    #pragma unroll
    for (int c = 0; c < 8; c++) {
        const int o = (b * 8 + c) * 256 + i;
        float Ac = pA[o], Bc = pB[o];
        B = fmaxf(B + Ac, Bc);
        A += Ac;
    }
    const float v = fmaxf(A, B);    // apply to v0 = 0
    out[PB + (size_t)b * 256 + i] = v;

    __shared__ float sh[256];
    sh[i] = v * Wo[i];
    __syncthreads();
    #pragma unroll
    for (int s = 128; s > 0; s >>= 1) {
        if (i < s) sh[i] += sh[i + s];
        __syncthreads();
    }
    if (i == 0) out[b] = 1.f / (1.f + __expf(-(sh[0] + bo[0])));
}

// ---------------- launch ---------------------------------------------------
extern "C" void kernel_launch(void* const* d_in, const int* in_sizes, int n_in,
                              void* d_out, int out_size)
{
    const float* x  = (const float*)d_in[0];
    const float* Wx = (const float*)d_in[1];
    const float* bx = (const float*)d_in[2];
    const float* W1 = (const float*)d_in[3];
    const float* b1 = (const float*)d_in[4];
    const float* W2 = (const float*)d_in[5];
    const float* b2 = (const float*)d_in[6];
    const float* W3 = (const float*)d_in[7];
    const float* b3 = (const float*)d_in[8];
    const float* W4 = (const float*)d_in[9];
    const float* b4 = (const float*)d_in[10];
    const float* W5 = (const float*)d_in[11];
    const float* b5 = (const float*)d_in[12];
    const float* Wo = (const float*)d_in[13];
    const float* bo = (const float*)d_in[14];
    float* out = (float*)d_out;

    void *p_sig, *p_a, *p_b, *p_c, *p_pA, *p_pB;
    void *p_WxT, *p_W1T, *p_W2T, *p_W3T, *p_W4T, *p_W5T;
    void *p_b1p, *p_b2p, *p_b3p, *p_b4p;
    cudaGetSymbolAddress(&p_sig, g_sig);
    cudaGetSymbolAddress(&p_a, g_a);
    cudaGetSymbolAddress(&p_b, g_b);
    cudaGetSymbolAddress(&p_c, g_c);
    cudaGetSymbolAddress(&p_pA, g_pA);
    cudaGetSymbolAddress(&p_pB, g_pB);
    cudaGetSymbolAddress(&p_WxT, g_WxT);
    cudaGetSymbolAddress(&p_W1T, g_W1T);
    cudaGetSymbolAddress(&p_W2T, g_W2T);
    cudaGetSymbolAddress(&p_W3T, g_W3T);
    cudaGetSymbolAddress(&p_W4T, g_W4T);
    cudaGetSymbolAddress(&p_W5T, g_W5T);
    cudaGetSymbolAddress(&p_b1p, g_b1p);
    cudaGetSymbolAddress(&p_b2p, g_b2p);
    cudaGetSymbolAddress(&p_b3p, g_b3p);
    cudaGetSymbolAddress(&p_b4p, g_b4p);
    float* sig = (float*)p_sig;
    float* va  = (float*)p_a;
    float* vb  = (float*)p_b;
    float* vc  = (float*)p_c;

    constexpr int S_K128_B128 = (128 + 128) * 132 * 4;  // 135168
    constexpr int S_K128_B64  = (128 + 64) * 132 * 4;   // 101376
    constexpr int S_K64_B128  = (128 + 128) * 68 * 4;   // 69632
    cudaFuncSetAttribute(mma_gemm<128, 256, 128, 1>, cudaFuncAttributeMaxDynamicSharedMemorySize, S_K128_B128);
    cudaFuncSetAttribute(mma_gemm<128, 128, 128, 2>, cudaFuncAttributeMaxDynamicSharedMemorySize, S_K128_B128);
    cudaFuncSetAttribute(mma_gemm<128, 64, 64, 2>,   cudaFuncAttributeMaxDynamicSharedMemorySize, S_K128_B64);
    cudaFuncSetAttribute(mma_gemm<64, 256, 128, 3>,  cudaFuncAttributeMaxDynamicSharedMemorySize, S_K64_B128);

    const int MT = BT / 128;   // 2048 row tiles

    prep_kernel<<<128, 256>>>(Wx, W1, b1, W2, b2, W3, b3, W4, b4, W5);

    // 1) sig(lin_x)
    mma_gemm<128, 256, 128, 1><<<dim3(2, MT), 256, S_K128_B128>>>(x, (const float*)p_WxT, bx, sig);
    // 2-5) MLP chain (padded widths)
    mma_gemm<128, 128, 128, 2><<<dim3(1, MT), 256, S_K128_B128>>>(x,  (const float*)p_W1T, (const float*)p_b1p, va);
    mma_gemm<128, 128, 128, 2><<<dim3(1, MT), 256, S_K128_B128>>>(va, (const float*)p_W2T, (const float*)p_b2p, vb);
    mma_gemm<128, 128, 128, 2><<<dim3(1, MT), 256, S_K128_B128>>>(vb, (const float*)p_W3T, (const float*)p_b3p, va);
    mma_gemm<128, 64, 64, 2><<<dim3(1, MT), 256, S_K128_B64>>>(va, (const float*)p_W4T, (const float*)p_b4p, vc);
    // 6) gate = sigmoid(.@W5+b5) * sig  (in place)
    mma_gemm<64, 256, 128, 3><<<dim3(2, MT), 256, S_K64_B128>>>(vc, (const float*)p_W5T, b5, sig);
    // 7) scan as parallel reduction + output head
    scan_part<<<PB * 8, 256>>>(sig, (float*)p_pA, (float*)p_pB);
    scan_fin<<<PB, 256>>>((const float*)p_pA, (const float*)p_pB, Wo, bo, out);
}

// round 6
// speedup vs baseline: 3.3908x; 1.2939x over previous
#include <cuda_runtime.h>
#include <cstdint>
#include <cstddef>

#define PB 256
#define PT 1024
#define PD 128
#define PH 256
#define BT (PB * PT)   // 262144 tokens

// ---------------- scratch (device globals; no cudaMalloc allowed) ----------
__device__ float g_gate[(size_t)BT * PH];  // gate (256 MB)
__device__ float g_a[(size_t)BT * 128];    // MLP ping (padded to 128)
__device__ float g_b[(size_t)BT * 128];    // MLP pong
__device__ float g_c[(size_t)BT * 64];     // layer-4 out (padded to 64)
__device__ float g_pA[2048 * 256];         // scan partials
__device__ float g_pB[2048 * 256];

// padded, transposed ([N, K] K-major) weights
__device__ float g_WxT[256 * 128];
__device__ float g_W1T[128 * 128];
__device__ float g_W2T[128 * 128];
__device__ float g_W3T[128 * 128];
__device__ float g_W4T[64 * 128];
__device__ float g_W5T[256 * 64];
__device__ float g_b1p[128], g_b2p[128], g_b3p[128], g_b4p[64];

__device__ __forceinline__ float sigf(float x) { return 1.f / (1.f + __expf(-x)); }

__device__ __forceinline__ uint32_t smem_u32(const void* p) {
    uint32_t a;
    asm("{ .reg .u64 t; cvta.to.shared.u64 t, %1; cvt.u32.u64 %0, t; }" : "=r"(a) : "l"(p));
    return a;
}
__device__ __forceinline__ void cp16(uint32_t dst, const void* src) {
    asm volatile("cp.async.ca.shared.global [%0], [%1], 16;" :: "r"(dst), "l"(src) : "memory");
}
__device__ __forceinline__ void cp_commit() {
    asm volatile("cp.async.commit_group;" ::: "memory");
}
template <int N>
__device__ __forceinline__ void cp_wait() {
    asm volatile("cp.async.wait_group %0;" :: "n"(N) : "memory");
}
__device__ __forceinline__ uint32_t f2tf(float x) {
    uint32_t u;
    asm("cvt.rna.tf32.f32 %0, %1;" : "=r"(u) : "f"(x));
    return u;
}
__device__ __forceinline__ void mma8(float* c, const uint32_t* a, uint32_t b0, uint32_t b1) {
    asm volatile(
        "mma.sync.aligned.m16n8k8.row.col.f32.tf32.tf32.f32 "
        "{%0,%1,%2,%3}, {%4,%5,%6,%7}, {%8,%9}, {%0,%1,%2,%3};"
        : "+f"(c[0]), "+f"(c[1]), "+f"(c[2]), "+f"(c[3])
        : "r"(a[0]), "r"(a[1]), "r"(a[2]), "r"(a[3]), "r"(b0), "r"(b1));
}

// ---------------- weight prep: transpose + pad -----------------------------
__global__ void prep_kernel(const float* __restrict__ Wx,
                            const float* __restrict__ W1, const float* __restrict__ b1,
                            const float* __restrict__ W2, const float* __restrict__ b2,
                            const float* __restrict__ W3, const float* __restrict__ b3,
                            const float* __restrict__ W4, const float* __restrict__ b4,
                            const float* __restrict__ W5)
{
    int t = blockIdx.x * blockDim.x + threadIdx.x;
    int S = gridDim.x * blockDim.x;
    for (int i = t; i < 256 * 128; i += S) { int n = i >> 7, k = i & 127; g_WxT[i] = Wx[k * 256 + n]; }
    for (int i = t; i < 128 * 128; i += S) { int n = i >> 7, k = i & 127; g_W1T[i] = (n < 100) ? W1[k * 100 + n] : 0.f; }
    for (int i = t; i < 128 * 128; i += S) { int n = i >> 7, k = i & 127; g_W2T[i] = (n < 100 && k < 100) ? W2[k * 100 + n] : 0.f; }
    for (int i = t; i < 128 * 128; i += S) { int n = i >> 7, k = i & 127; g_W3T[i] = (n < 100 && k < 100) ? W3[k * 100 + n] : 0.f; }
    for (int i = t; i < 64 * 128;  i += S) { int n = i >> 7, k = i & 127; g_W4T[i] = (n < 50 && k < 100) ? W4[k * 50 + n] : 0.f; }
    for (int i = t; i < 256 * 64;  i += S) { int n = i >> 6, k = i & 63;  g_W5T[i] = (k < 50) ? W5[k * 256 + n] : 0.f; }
    for (int i = t; i < 128; i += S) {
        g_b1p[i] = (i < 100) ? b1[i] : 0.f;
        g_b2p[i] = (i < 100) ? b2[i] : 0.f;
        g_b3p[i] = (i < 100) ? b3[i] : 0.f;
    }
    for (int i = t; i < 64; i += S) g_b4p[i] = (i < 50) ? b4[i] : 0.f;
}

// ---------------- pipelined mma.sync tf32 GEMM (relu) ----------------------
// C[128, BN] tile = relu(A[128, K] @ Bw[N, K]^T + bias); KC=32 2-stage pipeline.
template <int K, int NFULL, int BN>
__global__ void __launch_bounds__(256, 2)
mma_gemm(const float* __restrict__ A, const float* __restrict__ Bw,
         const float* __restrict__ bias, float* __restrict__ C)
{
    constexpr int KC = 32, PITCH = 36;
    constexpr int NCH = K / KC;
    constexpr int STAGE = (128 + BN) * PITCH;   // floats per stage
    constexpr int WN = BN / 2;
    constexpr int NT = WN / 8;
    extern __shared__ float sm[];
    const uint32_t sbase = smem_u32(sm);

    const int tid = threadIdx.x;
    const int lane = tid & 31, wid = tid >> 5;
    const int g = lane >> 2, tig = lane & 3;
    const int wm = wid & 3, wn = wid >> 2;
    const size_t rowBase = (size_t)blockIdx.y * 128;
    const int colBase = blockIdx.x * BN;

    auto load_chunk = [&](int ch, int st) {
        const int kc0 = ch * KC;
        const uint32_t sb = sbase + (uint32_t)(st * STAGE) * 4u;
        #pragma unroll
        for (int it = 0; it < 4; it++) {
            int id = tid + it * 256;
            int r = id >> 3, kv = (id & 7) * 4;
            cp16(sb + (uint32_t)(r * PITCH + kv) * 4u, A + (rowBase + r) * K + kc0 + kv);
        }
        #pragma unroll
        for (int it = 0; it < BN * 8 / 256; it++) {
            int id = tid + it * 256;
            int r = id >> 3, kv = (id & 7) * 4;
            cp16(sb + (uint32_t)((128 + r) * PITCH + kv) * 4u,
                 Bw + (size_t)(colBase + r) * K + kc0 + kv);
        }
        cp_commit();
    };

    float acc[2][NT][4];
    #pragma unroll
    for (int mt = 0; mt < 2; mt++)
        #pragma unroll
        for (int nt = 0; nt < NT; nt++)
            #pragma unroll
            for (int j = 0; j < 4; j++) acc[mt][nt][j] = 0.f;

    load_chunk(0, 0);
    load_chunk(1, 1);

    #pragma unroll
    for (int ch = 0; ch < NCH; ch++) {
        cp_wait<1>();
        __syncthreads();
        const float* As = sm + (ch & 1) * STAGE;
        const float* Bs = As + 128 * PITCH;
        #pragma unroll
        for (int s = 0; s < KC / 8; s++) {
            const int k0 = s * 8;
            uint32_t af[2][4];
            #pragma unroll
            for (int mt = 0; mt < 2; mt++) {
                const float* ap = As + (wm * 32 + mt * 16 + g) * PITCH + k0 + tig;
                af[mt][0] = f2tf(ap[0]);
                af[mt][1] = f2tf(ap[8 * PITCH]);
                af[mt][2] = f2tf(ap[4]);
                af[mt][3] = f2tf(ap[8 * PITCH + 4]);
            }
            #pragma unroll
            for (int nt = 0; nt < NT; nt++) {
                const float* bp = Bs + (wn * WN + nt * 8 + g) * PITCH + k0 + tig;
                uint32_t b0 = f2tf(bp[0]);
                uint32_t b1 = f2tf(bp[4]);
                mma8(acc[0][nt], af[0], b0, b1);
                mma8(acc[1][nt], af[1], b0, b1);
            }
        }
        __syncthreads();
        if (ch + 2 < NCH) load_chunk(ch + 2, ch & 1);
        else cp_commit();   // keep group accounting uniform
    }

    // ---- fused relu epilogue ----
    #pragma unroll
    for (int mt = 0; mt < 2; mt++) {
        #pragma unroll
        for (int nt = 0; nt < NT; nt++) {
            const int c0 = colBase + wn * WN + nt * 8 + 2 * tig;
            const float bx0 = __ldg(bias + c0), bx1 = __ldg(bias + c0 + 1);
            #pragma unroll
            for (int h = 0; h < 2; h++) {
                const size_t r = rowBase + wm * 32 + mt * 16 + g + h * 8;
                float v0 = fmaxf(acc[mt][nt][2 * h + 0] + bx0, 0.f);
                float v1 = fmaxf(acc[mt][nt][2 * h + 1] + bx1, 0.f);
                *(float2*)(C + r * NFULL + c0) = make_float2(v0, v1);
            }
        }
    }
}

// ---------------- fused gate GEMM ------------------------------------------
// gate[128, BN] = sigmoid(vc@W5 + b5) * sigmoid(x@Wx + bx)
// Unified 6-chunk pipeline: chunks 0-3 from (x, WxT) K=128, chunks 4-5 from
// (vc, W5T) K=64. 512 threads = 16 warps on 32x32 warp tiles.
__global__ void __launch_bounds__(512, 1)
gate_gemm(const float* __restrict__ x, const float* __restrict__ WxT,
          const float* __restrict__ bx,
          const float* __restrict__ vc, const float* __restrict__ W5T,
          const float* __restrict__ b5, float* __restrict__ C)
{
    constexpr int KC = 32, PITCH = 36, BN = 128;
    constexpr int STAGE = (128 + BN) * PITCH;
    constexpr int NCH = 6;
    constexpr int NT = 4;  // 32-wide warp N tile
    extern __shared__ float sm[];
    const uint32_t sbase = smem_u32(sm);

    const int tid = threadIdx.x;
    const int lane = tid & 31, wid = tid >> 5;
    const int g = lane >> 2, tig = lane & 3;
    const int wm = wid & 3, wn = wid >> 2;    // 4x4 warp grid
    const size_t rowBase = (size_t)blockIdx.y * 128;
    const int colBase = blockIdx.x * BN;

    auto load_chunk = [&](int ch, int st) {
        const float* Ag; const float* Bg; int Kp, kc0;
        if (ch < 4) { Ag = x;  Bg = WxT; Kp = 128; kc0 = ch * KC; }
        else        { Ag = vc; Bg = W5T; Kp = 64;  kc0 = (ch - 4) * KC; }
        const uint32_t sb = sbase + (uint32_t)(st * STAGE) * 4u;
        #pragma unroll
        for (int it = 0; it < 2; it++) {
            int id = tid + it * 512;
            int r = id >> 3, kv = (id & 7) * 4;
            cp16(sb + (uint32_t)(r * PITCH + kv) * 4u, Ag + (rowBase + r) * Kp + kc0 + kv);
        }
        #pragma unroll
        for (int it = 0; it < 2; it++) {
            int id = tid + it * 512;
            int r = id >> 3, kv = (id & 7) * 4;
            cp16(sb + (uint32_t)((128 + r) * PITCH + kv) * 4u,
                 Bg + (size_t)(colBase + r) * Kp + kc0 + kv);
        }
        cp_commit();
    };

    float acc1[2][NT][4], acc2[2][NT][4];
    #pragma unroll
    for (int mt = 0; mt < 2; mt++)
        #pragma unroll
        for (int nt = 0; nt < NT; nt++)
            #pragma unroll
            for (int j = 0; j < 4; j++) { acc1[mt][nt][j] = 0.f; acc2[mt][nt][j] = 0.f; }

    load_chunk(0, 0);
    load_chunk(1, 1);

    #pragma unroll
    for (int ch = 0; ch < NCH; ch++) {
        cp_wait<1>();
        __syncthreads();
        const float* As = sm + (ch & 1) * STAGE;
        const float* Bs = As + 128 * PITCH;
        #pragma unroll
        for (int s = 0; s < KC / 8; s++) {
            const int k0 = s * 8;
            uint32_t af[2][4];
            #pragma unroll
            for (int mt = 0; mt < 2; mt++) {
                const float* ap = As + (wm * 32 + mt * 16 + g) * PITCH + k0 + tig;
                af[mt][0] = f2tf(ap[0]);
                af[mt][1] = f2tf(ap[8 * PITCH]);
                af[mt][2] = f2tf(ap[4]);
                af[mt][3] = f2tf(ap[8 * PITCH + 4]);
            }
            #pragma unroll
            for (int nt = 0; nt < NT; nt++) {
                const float* bp = Bs + (wn * 32 + nt * 8 + g) * PITCH + k0 + tig;
                uint32_t b0 = f2tf(bp[0]);
                uint32_t b1 = f2tf(bp[4]);
                if (ch < 4) {
                    mma8(acc1[0][nt], af[0], b0, b1);
                    mma8(acc1[1][nt], af[1], b0, b1);
                } else {
                    mma8(acc2[0][nt], af[0], b0, b1);
                    mma8(acc2[1][nt], af[1], b0, b1);
                }
            }
        }
        __syncthreads();
        if (ch + 2 < NCH) load_chunk(ch + 2, ch & 1);
        else cp_commit();
    }

    // gate = sigmoid(acc2 + b5) * sigmoid(acc1 + bx)
    #pragma unroll
    for (int mt = 0; mt < 2; mt++) {
        #pragma unroll
        for (int nt = 0; nt < NT; nt++) {
            const int c0 = colBase + wn * 32 + nt * 8 + 2 * tig;
            const float bx0 = __ldg(bx + c0), bx1 = __ldg(bx + c0 + 1);
            const float b50 = __ldg(b5 + c0), b51 = __ldg(b5 + c0 + 1);
            #pragma unroll
            for (int h = 0; h < 2; h++) {
                const size_t r = rowBase + wm * 32 + mt * 16 + g + h * 8;
                float v0 = sigf(acc2[mt][nt][2 * h + 0] + b50) * sigf(acc1[mt][nt][2 * h + 0] + bx0);
                float v1 = sigf(acc2[mt][nt][2 * h + 1] + b51) * sigf(acc1[mt][nt][2 * h + 1] + bx1);
                *(float2*)(C + r * PH + c0) = make_float2(v0, v1);
            }
        }
    }
}

// ---------------- scan as max-plus reduction --------------------------------
// Per final coordinate i the recurrence follows a diagonal scalar chain
// v <- max(v + a_t, 0) with a_t = gate[b][t][(i + t + 1) & 255].
// f(v)=max(v+A,B) composes: (A,B)*(A',B') = (A+A', max(B+A', B')).
__global__ void __launch_bounds__(256)
scan_part(const float* __restrict__ gate, float* __restrict__ pA, float* __restrict__ pB)
{
    const int b = blockIdx.x >> 3, c = blockIdx.x & 7;
    const int i = threadIdx.x;
    const float* gb = gate + ((size_t)b << 18);
    float Aacc = 0.f, Bacc = -3.0e38f;
    const int t0 = c * 128;
    #pragma unroll 8
    for (int t = t0; t < t0 + 128; t++) {
        float val = gb[(size_t)t * 256 + ((i + t + 1) & 255)];
        Aacc += val;
        Bacc = fmaxf(Bacc + val, 0.f);
    }
    const int o = blockIdx.x * 256 + i;
    pA[o] = Aacc;
    pB[o] = Bacc;
}

__global__ void __launch_bounds__(256)
scan_fin(const float* __restrict__ pA, const float* __restrict__ pB,
         const float* __restrict__ Wo, const float* __restrict__ bo,
         float* __restrict__ out)
{
    const int b = blockIdx.x, i = threadIdx.x;
    float A = 0.f, B = -3.0e38f;
    #pragma unroll
    for (int c = 0; c < 8; c++) {
        const int o = (b * 8 + c) * 256 + i;
        float Ac = pA[o], Bc = pB[o];
        B = fmaxf(B + Ac, Bc);
        A += Ac;
    }
    const float v = fmaxf(A, B);    // apply to v0 = 0
    out[PB + (size_t)b * 256 + i] = v;

    __shared__ float sh[256];
    sh[i] = v * Wo[i];
    __syncthreads();
    #pragma unroll
    for (int s = 128; s > 0; s >>= 1) {
        if (i < s) sh[i] += sh[i + s];
        __syncthreads();
    }
    if (i == 0) out[b] = 1.f / (1.f + __expf(-(sh[0] + bo[0])));
}

// ---------------- launch ---------------------------------------------------
extern "C" void kernel_launch(void* const* d_in, const int* in_sizes, int n_in,
                              void* d_out, int out_size)
{
    const float* x  = (const float*)d_in[0];
    const float* Wx = (const float*)d_in[1];
    const float* bx = (const float*)d_in[2];
    const float* W1 = (const float*)d_in[3];
    const float* b1 = (const float*)d_in[4];
    const float* W2 = (const float*)d_in[5];
    const float* b2 = (const float*)d_in[6];
    const float* W3 = (const float*)d_in[7];
    const float* b3 = (const float*)d_in[8];
    const float* W4 = (const float*)d_in[9];
    const float* b4 = (const float*)d_in[10];
    const float* W5 = (const float*)d_in[11];
    const float* b5 = (const float*)d_in[12];
    const float* Wo = (const float*)d_in[13];
    const float* bo = (const float*)d_in[14];
    float* out = (float*)d_out;

    void *p_gate, *p_a, *p_b, *p_c, *p_pA, *p_pB;
    void *p_WxT, *p_W1T, *p_W2T, *p_W3T, *p_W4T, *p_W5T;
    void *p_b1p, *p_b2p, *p_b3p, *p_b4p;
    cudaGetSymbolAddress(&p_gate, g_gate);
    cudaGetSymbolAddress(&p_a, g_a);
    cudaGetSymbolAddress(&p_b, g_b);
    cudaGetSymbolAddress(&p_c, g_c);
    cudaGetSymbolAddress(&p_pA, g_pA);
    cudaGetSymbolAddress(&p_pB, g_pB);
    cudaGetSymbolAddress(&p_WxT, g_WxT);
    cudaGetSymbolAddress(&p_W1T, g_W1T);
    cudaGetSymbolAddress(&p_W2T, g_W2T);
    cudaGetSymbolAddress(&p_W3T, g_W3T);
    cudaGetSymbolAddress(&p_W4T, g_W4T);
    cudaGetSymbolAddress(&p_W5T, g_W5T);
    cudaGetSymbolAddress(&p_b1p, g_b1p);
    cudaGetSymbolAddress(&p_b2p, g_b2p);
    cudaGetSymbolAddress(&p_b3p, g_b3p);
    cudaGetSymbolAddress(&p_b4p, g_b4p);
    float* gate = (float*)p_gate;
    float* va   = (float*)p_a;
    float* vb   = (float*)p_b;
    float* vc   = (float*)p_c;

    // dyn smem: 2 stages x (128 + BN) rows x 36 floats
    constexpr int S_B128 = 2 * (128 + 128) * 36 * 4;  // 73728
    constexpr int S_B64  = 2 * (128 + 64) * 36 * 4;   // 55296
    cudaFuncSetAttribute(mma_gemm<128, 128, 128>, cudaFuncAttributeMaxDynamicSharedMemorySize, S_B128);
    cudaFuncSetAttribute(mma_gemm<128, 64, 64>,   cudaFuncAttributeMaxDynamicSharedMemorySize, S_B64);
    cudaFuncSetAttribute(gate_gemm, cudaFuncAttributeMaxDynamicSharedMemorySize, S_B128);

    const int MT = BT / 128;   // 2048 row tiles

    prep_kernel<<<128, 256>>>(Wx, W1, b1, W2, b2, W3, b3, W4, b4, W5);

    // MLP chain (padded widths)
    mma_gemm<128, 128, 128><<<dim3(1, MT), 256, S_B128>>>(x,  (const float*)p_W1T, (const float*)p_b1p, va);
    mma_gemm<128, 128, 128><<<dim3(1, MT), 256, S_B128>>>(va, (const float*)p_W2T, (const float*)p_b2p, vb);
    mma_gemm<128, 128, 128><<<dim3(1, MT), 256, S_B128>>>(vb, (const float*)p_W3T, (const float*)p_b3p, va);
    mma_gemm<128, 64, 64><<<dim3(1, MT), 256, S_B64>>>(va, (const float*)p_W4T, (const float*)p_b4p, vc);
    // fused gate: sigmoid(vc@W5+b5) * sigmoid(x@Wx+bx)
    gate_gemm<<<dim3(2, MT), 512, S_B128>>>(x, (const float*)p_WxT, bx,
                                            vc, (const float*)p_W5T, b5, gate);
    // scan as parallel reduction + output head
    scan_part<<<PB * 8, 256>>>(gate, (float*)p_pA, (float*)p_pB);
    scan_fin<<<PB, 256>>>((const float*)p_pA, (const float*)p_pB, Wo, bo, out);
}

// round 7
// speedup vs baseline: 4.7104x; 1.3892x over previous
#include <cuda_runtime.h>
#include <cuda_bf16.h>
#include <cstdint>
#include <cstddef>

#define PB 256
#define PT 1024
#define PD 128
#define PH 256
#define BT (PB * PT)   // 262144 tokens

// ---------------- scratch (device globals; no cudaMalloc allowed) ----------
__device__ __nv_bfloat16 g_gate[(size_t)BT * PH];  // gate bf16 (128 MB)
__device__ __nv_bfloat16 g_xb[(size_t)BT * 128];   // x in bf16
__device__ __nv_bfloat16 g_a[(size_t)BT * 128];    // MLP ping (padded)
__device__ __nv_bfloat16 g_b[(size_t)BT * 128];    // MLP pong
__device__ __nv_bfloat16 g_c[(size_t)BT * 64];     // layer-4 out (padded)
__device__ float g_pA[2048 * 256];                 // scan partials (fp32)
__device__ float g_pB[2048 * 256];

// padded, transposed ([N, K] K-major) bf16 weights
__device__ __nv_bfloat16 g_WxT[256 * 128];
__device__ __nv_bfloat16 g_W1T[128 * 128];
__device__ __nv_bfloat16 g_W2T[128 * 128];
__device__ __nv_bfloat16 g_W3T[128 * 128];
__device__ __nv_bfloat16 g_W4T[64 * 128];
__device__ __nv_bfloat16 g_W5T[256 * 64];
__device__ float g_b1p[128], g_b2p[128], g_b3p[128], g_b4p[64];

__device__ __forceinline__ float sigf(float x) { return 1.f / (1.f + __expf(-x)); }

__device__ __forceinline__ uint32_t smem_u32(const void* p) {
    uint32_t a;
    asm("{ .reg .u64 t; cvta.to.shared.u64 t, %1; cvt.u32.u64 %0, t; }" : "=r"(a) : "l"(p));
    return a;
}
__device__ __forceinline__ void cp16(uint32_t dst, const void* src) {
    asm volatile("cp.async.ca.shared.global [%0], [%1], 16;" :: "r"(dst), "l"(src) : "memory");
}
__device__ __forceinline__ void cp_commit() {
    asm volatile("cp.async.commit_group;" ::: "memory");
}
template <int N>
__device__ __forceinline__ void cp_wait() {
    asm volatile("cp.async.wait_group %0;" :: "n"(N) : "memory");
}
// bf16 mma: D[16x8] += A[16x16] B[16x8]
__device__ __forceinline__ void mma16(float* c, const uint32_t* a, uint32_t b0, uint32_t b1) {
    asm volatile(
        "mma.sync.aligned.m16n8k16.row.col.f32.bf16.bf16.f32 "
        "{%0,%1,%2,%3}, {%4,%5,%6,%7}, {%8,%9}, {%0,%1,%2,%3};"
        : "+f"(c[0]), "+f"(c[1]), "+f"(c[2]), "+f"(c[3])
        : "r"(a[0]), "r"(a[1]), "r"(a[2]), "r"(a[3]), "r"(b0), "r"(b1));
}
__device__ __forceinline__ uint32_t ldu32(const __nv_bfloat16* p) {
    return *(const uint32_t*)p;
}

// ---------------- weight prep: transpose + pad + bf16 ----------------------
__global__ void prep_kernel(const float* __restrict__ Wx,
                            const float* __restrict__ W1, const float* __restrict__ b1,
                            const float* __restrict__ W2, const float* __restrict__ b2,
                            const float* __restrict__ W3, const float* __restrict__ b3,
                            const float* __restrict__ W4, const float* __restrict__ b4,
                            const float* __restrict__ W5)
{
    int t = blockIdx.x * blockDim.x + threadIdx.x;
    int S = gridDim.x * blockDim.x;
    for (int i = t; i < 256 * 128; i += S) { int n = i >> 7, k = i & 127; g_WxT[i] = __float2bfloat16(Wx[k * 256 + n]); }
    for (int i = t; i < 128 * 128; i += S) { int n = i >> 7, k = i & 127; g_W1T[i] = __float2bfloat16((n < 100) ? W1[k * 100 + n] : 0.f); }
    for (int i = t; i < 128 * 128; i += S) { int n = i >> 7, k = i & 127; g_W2T[i] = __float2bfloat16((n < 100 && k < 100) ? W2[k * 100 + n] : 0.f); }
    for (int i = t; i < 128 * 128; i += S) { int n = i >> 7, k = i & 127; g_W3T[i] = __float2bfloat16((n < 100 && k < 100) ? W3[k * 100 + n] : 0.f); }
    for (int i = t; i < 64 * 128;  i += S) { int n = i >> 7, k = i & 127; g_W4T[i] = __float2bfloat16((n < 50 && k < 100) ? W4[k * 50 + n] : 0.f); }
    for (int i = t; i < 256 * 64;  i += S) { int n = i >> 6, k = i & 63;  g_W5T[i] = __float2bfloat16((k < 50) ? W5[k * 256 + n] : 0.f); }
    for (int i = t; i < 128; i += S) {
        g_b1p[i] = (i < 100) ? b1[i] : 0.f;
        g_b2p[i] = (i < 100) ? b2[i] : 0.f;
        g_b3p[i] = (i < 100) ? b3[i] : 0.f;
    }
    for (int i = t; i < 64; i += S) g_b4p[i] = (i < 50) ? b4[i] : 0.f;
}

// ---------------- x -> bf16 -------------------------------------------------
__global__ void __launch_bounds__(256)
conv_x(const float* __restrict__ x, __nv_bfloat16* __restrict__ xb)
{
    size_t i = ((size_t)blockIdx.x * 256 + threadIdx.x) * 4;
    float4 v = *(const float4*)(x + i);
    __nv_bfloat162* o = (__nv_bfloat162*)(xb + i);
    o[0] = __floats2bfloat162_rn(v.x, v.y);
    o[1] = __floats2bfloat162_rn(v.z, v.w);
}

// ---------------- pipelined bf16 mma GEMM (relu) ---------------------------
// C[128, BN] = relu(A[128, K] @ Bw[N, K]^T + bias), bf16 in/out, fp32 acc.
// KC=64 bf16 per chunk, 2-stage cp.async pipeline, pitch 72 elements.
template <int K, int NFULL, int BN>
__global__ void __launch_bounds__(256, 2)
mma_gemm(const __nv_bfloat16* __restrict__ A, const __nv_bfloat16* __restrict__ Bw,
         const float* __restrict__ bias, __nv_bfloat16* __restrict__ C)
{
    constexpr int KC = 64, PITCH = 72;
    constexpr int NCH = K / KC;
    constexpr int STAGE = (128 + BN) * PITCH;   // bf16 elements per stage
    constexpr int WN = BN / 2;
    constexpr int NT = WN / 8;
    extern __shared__ __nv_bfloat16 smb[];
    const uint32_t sbase = smem_u32(smb);

    const int tid = threadIdx.x;
    const int lane = tid & 31, wid = tid >> 5;
    const int g = lane >> 2, tig = lane & 3;
    const int wm = wid & 3, wn = wid >> 2;
    const size_t rowBase = (size_t)blockIdx.y * 128;
    const int colBase = blockIdx.x * BN;

    auto load_chunk = [&](int ch, int st) {
        const int kc0 = ch * KC;
        const uint32_t sb = sbase + (uint32_t)(st * STAGE) * 2u;
        #pragma unroll
        for (int it = 0; it < 4; it++) {              // A: 128 rows x 8 segs
            int id = tid + it * 256;
            int r = id >> 3, seg = (id & 7) * 8;
            cp16(sb + (uint32_t)(r * PITCH + seg) * 2u, A + (rowBase + r) * K + kc0 + seg);
        }
        #pragma unroll
        for (int it = 0; it < BN * 8 / 256; it++) {   // B: BN rows x 8 segs
            int id = tid + it * 256;
            int r = id >> 3, seg = (id & 7) * 8;
            cp16(sb + (uint32_t)((128 + r) * PITCH + seg) * 2u,
                 Bw + (size_t)(colBase + r) * K + kc0 + seg);
        }
        cp_commit();
    };

    float acc[2][NT][4];
    #pragma unroll
    for (int mt = 0; mt < 2; mt++)
        #pragma unroll
        for (int nt = 0; nt < NT; nt++)
            #pragma unroll
            for (int j = 0; j < 4; j++) acc[mt][nt][j] = 0.f;

    load_chunk(0, 0);
    if (NCH > 1) load_chunk(1, 1); else cp_commit();

    #pragma unroll
    for (int ch = 0; ch < NCH; ch++) {
        cp_wait<1>();
        __syncthreads();
        const __nv_bfloat16* As = smb + (ch & 1) * STAGE;
        const __nv_bfloat16* Bs = As + 128 * PITCH;
        #pragma unroll
        for (int s = 0; s < KC / 16; s++) {
            const int k0 = s * 16;
            uint32_t af[2][4];
            #pragma unroll
            for (int mt = 0; mt < 2; mt++) {
                const __nv_bfloat16* ap = As + (wm * 32 + mt * 16 + g) * PITCH + k0 + 2 * tig;
                af[mt][0] = ldu32(ap);
                af[mt][1] = ldu32(ap + 8 * PITCH);
                af[mt][2] = ldu32(ap + 8);
                af[mt][3] = ldu32(ap + 8 * PITCH + 8);
            }
            #pragma unroll
            for (int nt = 0; nt < NT; nt++) {
                const __nv_bfloat16* bp = Bs + (wn * WN + nt * 8 + g) * PITCH + k0 + 2 * tig;
                uint32_t b0 = ldu32(bp);
                uint32_t b1 = ldu32(bp + 8);
                mma16(acc[0][nt], af[0], b0, b1);
                mma16(acc[1][nt], af[1], b0, b1);
            }
        }
        __syncthreads();
        if (ch + 2 < NCH) load_chunk(ch + 2, ch & 1);
        else cp_commit();
    }

    // ---- fused relu epilogue, bf16 pair stores ----
    #pragma unroll
    for (int mt = 0; mt < 2; mt++) {
        #pragma unroll
        for (int nt = 0; nt < NT; nt++) {
            const int c0 = colBase + wn * WN + nt * 8 + 2 * tig;
            const float bx0 = __ldg(bias + c0), bx1 = __ldg(bias + c0 + 1);
            #pragma unroll
            for (int h = 0; h < 2; h++) {
                const size_t r = rowBase + wm * 32 + mt * 16 + g + h * 8;
                float v0 = fmaxf(acc[mt][nt][2 * h + 0] + bx0, 0.f);
                float v1 = fmaxf(acc[mt][nt][2 * h + 1] + bx1, 0.f);
                *(__nv_bfloat162*)(C + r * NFULL + c0) = __floats2bfloat162_rn(v0, v1);
            }
        }
    }
}

// ---------------- fused gate GEMM (bf16) ------------------------------------
// gate = sigmoid(vc@W5 + b5) * sigmoid(x@Wx + bx), stored bf16.
// 3-chunk pipeline: chunks 0-1 (x_bf, WxT, K=128), chunk 2 (vc, W5T, K=64).
__global__ void __launch_bounds__(512, 1)
gate_gemm(const __nv_bfloat16* __restrict__ xb, const __nv_bfloat16* __restrict__ WxT,
          const float* __restrict__ bx,
          const __nv_bfloat16* __restrict__ vc, const __nv_bfloat16* __restrict__ W5T,
          const float* __restrict__ b5, __nv_bfloat16* __restrict__ C)
{
    constexpr int KC = 64, PITCH = 72, BN = 128;
    constexpr int STAGE = (128 + BN) * PITCH;
    constexpr int NCH = 3;
    constexpr int NT = 4;  // 32-wide warp N tile
    extern __shared__ __nv_bfloat16 smb[];
    const uint32_t sbase = smem_u32(smb);

    const int tid = threadIdx.x;
    const int lane = tid & 31, wid = tid >> 5;
    const int g = lane >> 2, tig = lane & 3;
    const int wm = wid & 3, wn = wid >> 2;    // 4x4 warp grid
    const size_t rowBase = (size_t)blockIdx.y * 128;
    const int colBase = blockIdx.x * BN;

    auto load_chunk = [&](int ch, int st) {
        const __nv_bfloat16* Ag; const __nv_bfloat16* Bg; int Kp, kc0;
        if (ch < 2) { Ag = xb; Bg = WxT; Kp = 128; kc0 = ch * KC; }
        else        { Ag = vc; Bg = W5T; Kp = 64;  kc0 = 0; }
        const uint32_t sb = sbase + (uint32_t)(st * STAGE) * 2u;
        #pragma unroll
        for (int it = 0; it < 2; it++) {
            int id = tid + it * 512;
            int r = id >> 3, seg = (id & 7) * 8;
            cp16(sb + (uint32_t)(r * PITCH + seg) * 2u, Ag + (rowBase + r) * Kp + kc0 + seg);
        }
        #pragma unroll
        for (int it = 0; it < 2; it++) {
            int id = tid + it * 512;
            int r = id >> 3, seg = (id & 7) * 8;
            cp16(sb + (uint32_t)((128 + r) * PITCH + seg) * 2u,
                 Bg + (size_t)(colBase + r) * Kp + kc0 + seg);
        }
        cp_commit();
    };

    float acc1[2][NT][4], acc2[2][NT][4];
    #pragma unroll
    for (int mt = 0; mt < 2; mt++)
        #pragma unroll
        for (int nt = 0; nt < NT; nt++)
            #pragma unroll
            for (int j = 0; j < 4; j++) { acc1[mt][nt][j] = 0.f; acc2[mt][nt][j] = 0.f; }

    load_chunk(0, 0);
    load_chunk(1, 1);

    #pragma unroll
    for (int ch = 0; ch < NCH; ch++) {
        cp_wait<1>();
        __syncthreads();
        const __nv_bfloat16* As = smb + (ch & 1) * STAGE;
        const __nv_bfloat16* Bs = As + 128 * PITCH;
        #pragma unroll
        for (int s = 0; s < KC / 16; s++) {
            const int k0 = s * 16;
            uint32_t af[2][4];
            #pragma unroll
            for (int mt = 0; mt < 2; mt++) {
                const __nv_bfloat16* ap = As + (wm * 32 + mt * 16 + g) * PITCH + k0 + 2 * tig;
                af[mt][0] = ldu32(ap);
                af[mt][1] = ldu32(ap + 8 * PITCH);
                af[mt][2] = ldu32(ap + 8);
                af[mt][3] = ldu32(ap + 8 * PITCH + 8);
            }
            #pragma unroll
            for (int nt = 0; nt < NT; nt++) {
                const __nv_bfloat16* bp = Bs + (wn * 32 + nt * 8 + g) * PITCH + k0 + 2 * tig;
                uint32_t b0 = ldu32(bp);
                uint32_t b1 = ldu32(bp + 8);
                if (ch < 2) {
                    mma16(acc1[0][nt], af[0], b0, b1);
                    mma16(acc1[1][nt], af[1], b0, b1);
                } else {
                    mma16(acc2[0][nt], af[0], b0, b1);
                    mma16(acc2[1][nt], af[1], b0, b1);
                }
            }
        }
        __syncthreads();
        if (ch + 2 < NCH) load_chunk(ch + 2, ch & 1);
        else cp_commit();
    }

    // gate = sigmoid(acc2 + b5) * sigmoid(acc1 + bx), bf16 store
    #pragma unroll
    for (int mt = 0; mt < 2; mt++) {
        #pragma unroll
        for (int nt = 0; nt < NT; nt++) {
            const int c0 = colBase + wn * 32 + nt * 8 + 2 * tig;
            const float bx0 = __ldg(bx + c0), bx1 = __ldg(bx + c0 + 1);
            const float b50 = __ldg(b5 + c0), b51 = __ldg(b5 + c0 + 1);
            #pragma unroll
            for (int h = 0; h < 2; h++) {
                const size_t r = rowBase + wm * 32 + mt * 16 + g + h * 8;
                float v0 = sigf(acc2[mt][nt][2 * h + 0] + b50) * sigf(acc1[mt][nt][2 * h + 0] + bx0);
                float v1 = sigf(acc2[mt][nt][2 * h + 1] + b51) * sigf(acc1[mt][nt][2 * h + 1] + bx1);
                *(__nv_bfloat162*)(C + r * PH + c0) = __floats2bfloat162_rn(v0, v1);
            }
        }
    }
}

// ---------------- scan as max-plus reduction --------------------------------
// v <- max(v + a_t, 0), a_t = gate[b][t][(i + t + 1) & 255].
// f(v)=max(v+A,B) composes: (A,B)*(A',B') = (A+A', max(B+A', B')).
__global__ void __launch_bounds__(256)
scan_part(const __nv_bfloat16* __restrict__ gate, float* __restrict__ pA, float* __restrict__ pB)
{
    const int b = blockIdx.x >> 3, c = blockIdx.x & 7;
    const int i = threadIdx.x;
    const __nv_bfloat16* gb = gate + ((size_t)b << 18);
    float Aacc = 0.f, Bacc = -3.0e38f;
    const int t0 = c * 128;
    #pragma unroll 8
    for (int t = t0; t < t0 + 128; t++) {
        float val = __bfloat162float(gb[(size_t)t * 256 + ((i + t + 1) & 255)]);
        Aacc += val;
        Bacc = fmaxf(Bacc + val, 0.f);
    }
    const int o = blockIdx.x * 256 + i;
    pA[o] = Aacc;
    pB[o] = Bacc;
}

__global__ void __launch_bounds__(256)
scan_fin(const float* __restrict__ pA, const float* __restrict__ pB,
         const float* __restrict__ Wo, const float* __restrict__ bo,
         float* __restrict__ out)
{
    const int b = blockIdx.x, i = threadIdx.x;
    float A = 0.f, B = -3.0e38f;
    #pragma unroll
    for (int c = 0; c < 8; c++) {
        const int o = (b * 8 + c) * 256 + i;
        float Ac = pA[o], Bc = pB[o];
        B = fmaxf(B + Ac, Bc);
        A += Ac;
    }
    const float v = fmaxf(A, B);    // apply to v0 = 0
    out[PB + (size_t)b * 256 + i] = v;

    __shared__ float sh[256];
    sh[i] = v * Wo[i];
    __syncthreads();
    #pragma unroll
    for (int s = 128; s > 0; s >>= 1) {
        if (i < s) sh[i] += sh[i + s];
        __syncthreads();
    }
    if (i == 0) out[b] = 1.f / (1.f + __expf(-(sh[0] + bo[0])));
}

// ---------------- launch ---------------------------------------------------
extern "C" void kernel_launch(void* const* d_in, const int* in_sizes, int n_in,
                              void* d_out, int out_size)
{
    const float* x  = (const float*)d_in[0];
    const float* Wx = (const float*)d_in[1];
    const float* bx = (const float*)d_in[2];
    const float* W1 = (const float*)d_in[3];
    const float* b1 = (const float*)d_in[4];
    const float* W2 = (const float*)d_in[5];
    const float* b2 = (const float*)d_in[6];
    const float* W3 = (const float*)d_in[7];
    const float* b3 = (const float*)d_in[8];
    const float* W4 = (const float*)d_in[9];
    const float* b4 = (const float*)d_in[10];
    const float* W5 = (const float*)d_in[11];
    const float* b5 = (const float*)d_in[12];
    const float* Wo = (const float*)d_in[13];
    const float* bo = (const float*)d_in[14];
    float* out = (float*)d_out;

    void *p_gate, *p_xb, *p_a, *p_b, *p_c, *p_pA, *p_pB;
    void *p_WxT, *p_W1T, *p_W2T, *p_W3T, *p_W4T, *p_W5T;
    void *p_b1p, *p_b2p, *p_b3p, *p_b4p;
    cudaGetSymbolAddress(&p_gate, g_gate);
    cudaGetSymbolAddress(&p_xb, g_xb);
    cudaGetSymbolAddress(&p_a, g_a);
    cudaGetSymbolAddress(&p_b, g_b);
    cudaGetSymbolAddress(&p_c, g_c);
    cudaGetSymbolAddress(&p_pA, g_pA);
    cudaGetSymbolAddress(&p_pB, g_pB);
    cudaGetSymbolAddress(&p_WxT, g_WxT);
    cudaGetSymbolAddress(&p_W1T, g_W1T);
    cudaGetSymbolAddress(&p_W2T, g_W2T);
    cudaGetSymbolAddress(&p_W3T, g_W3T);
    cudaGetSymbolAddress(&p_W4T, g_W4T);
    cudaGetSymbolAddress(&p_W5T, g_W5T);
    cudaGetSymbolAddress(&p_b1p, g_b1p);
    cudaGetSymbolAddress(&p_b2p, g_b2p);
    cudaGetSymbolAddress(&p_b3p, g_b3p);
    cudaGetSymbolAddress(&p_b4p, g_b4p);
    __nv_bfloat16* gate = (__nv_bfloat16*)p_gate;
    __nv_bfloat16* xb   = (__nv_bfloat16*)p_xb;
    __nv_bfloat16* va   = (__nv_bfloat16*)p_a;
    __nv_bfloat16* vb   = (__nv_bfloat16*)p_b;
    __nv_bfloat16* vc   = (__nv_bfloat16*)p_c;

    // dyn smem: 2 stages x (128 + BN) rows x 72 bf16
    constexpr int S_B128 = 2 * (128 + 128) * 72 * 2;  // 73728
    constexpr int S_B64  = 2 * (128 + 64) * 72 * 2;   // 55296
    cudaFuncSetAttribute(mma_gemm<128, 128, 128>, cudaFuncAttributeMaxDynamicSharedMemorySize, S_B128);
    cudaFuncSetAttribute(mma_gemm<128, 64, 64>,   cudaFuncAttributeMaxDynamicSharedMemorySize, S_B64);
    cudaFuncSetAttribute(gate_gemm, cudaFuncAttributeMaxDynamicSharedMemorySize, S_B128);

    const int MT = BT / 128;   // 2048 row tiles

    prep_kernel<<<128, 256>>>(Wx, W1, b1, W2, b2, W3, b3, W4, b4, W5);
    conv_x<<<BT * 128 / (256 * 4), 256>>>(x, xb);

    // MLP chain (padded widths), bf16
    mma_gemm<128, 128, 128><<<dim3(1, MT), 256, S_B128>>>(xb, (const __nv_bfloat16*)p_W1T, (const float*)p_b1p, va);
    mma_gemm<128, 128, 128><<<dim3(1, MT), 256, S_B128>>>(va, (const __nv_bfloat16*)p_W2T, (const float*)p_b2p, vb);
    mma_gemm<128, 128, 128><<<dim3(1, MT), 256, S_B128>>>(vb, (const __nv_bfloat16*)p_W3T, (const float*)p_b3p, va);
    mma_gemm<128, 64, 64><<<dim3(1, MT), 256, S_B64>>>(va, (const __nv_bfloat16*)p_W4T, (const float*)p_b4p, vc);
    // fused gate: sigmoid(vc@W5+b5) * sigmoid(x@Wx+bx)
    gate_gemm<<<dim3(2, MT), 512, S_B128>>>(xb, (const __nv_bfloat16*)p_WxT, bx,
                                            vc, (const __nv_bfloat16*)p_W5T, b5, gate);
    // scan as parallel reduction + output head
    scan_part<<<PB * 8, 256>>>(gate, (float*)p_pA, (float*)p_pB);
    scan_fin<<<PB, 256>>>((const float*)p_pA, (const float*)p_pB, Wo, bo, out);
}